// round 9
// baseline (speedup 1.0000x reference)
#include <cuda_runtime.h>
#include <cstdint>
#include <cstddef>

#define T_STEPS    64
#define INPUT_BITS 1024
#define N_STATE    2048
#define N_OUT      256
#define HASH       65536

#define NCTAS    8
#define THREADS  128                     // 8 CTAs * 128 thr * 2 neurons = 2048
#define WARPS    (THREADS / 32)          // 4 warps -> 8 state words per CTA

// Unified smem bit store (per CTA):
//   words [0, 2048)      : packed window bits, 32 words per step t (all 64 steps)
//   words [2048, 2112)   : state buffer 0 (64 words)
//   words [2112, 2176)   : state buffer 1 (64 words)
#define WIN_WORDS   2048
#define STATE_BASE  2048
#define SBITS_WORDS 2176
#define STEP_TX_BYTES 256                // 64 words * 4B arrive per CTA per step

// -------- helpers ------------------------------------------------------------
__device__ __forceinline__ uint32_t smem_u32(const void* p) {
    uint32_t a;
    asm("{ .reg .u64 t; cvta.to.shared.u64 t, %1; cvt.u32.u64 %0, t; }"
        : "=r"(a) : "l"(p));
    return a;
}
__device__ __forceinline__ uint32_t cluster_rank() {
    uint32_t r;
    asm("mov.u32 %0, %%cluster_ctarank;" : "=r"(r));
    return r;
}
__device__ __forceinline__ uint32_t mapa_u32(uint32_t laddr, uint32_t rank) {
    uint32_t raddr;
    asm("mapa.shared::cluster.u32 %0, %1, %2;" : "=r"(raddr) : "r"(laddr), "r"(rank));
    return raddr;
}
// Remote smem 8-byte store that signals the remote mbarrier with 8 tx bytes.
__device__ __forceinline__ void st_async_u64(uint32_t rdata, unsigned long long v,
                                             uint32_t rmbar) {
    asm volatile(
        "st.async.shared::cluster.mbarrier::complete_tx::bytes.b64 [%0], %1, [%2];"
        :: "r"(rdata), "l"(v), "r"(rmbar) : "memory");
}
__device__ __forceinline__ void mbar_init(uint32_t mbar, unsigned count) {
    asm volatile("mbarrier.init.shared.b64 [%0], %1;" :: "r"(mbar), "r"(count) : "memory");
}
__device__ __forceinline__ void mbar_arrive(uint32_t mbar) {
    asm volatile("mbarrier.arrive.shared.b64 _, [%0];" :: "r"(mbar) : "memory");
}
__device__ __forceinline__ void mbar_arm_tx(uint32_t mbar, unsigned tx) {
    asm volatile("mbarrier.arrive.expect_tx.shared.b64 _, [%0], %1;"
                 :: "r"(mbar), "r"(tx) : "memory");
}
__device__ __forceinline__ void mbar_wait_parity(uint32_t mbar, unsigned parity) {
    unsigned done;
    asm volatile(
        "{\n\t.reg .pred p;\n\t"
        "mbarrier.try_wait.parity.acquire.cta.shared::cta.b64 p, [%1], %2;\n\t"
        "selp.b32 %0, 1, 0, p;\n\t}"
        : "=r"(done) : "r"(mbar), "r"(parity) : "memory");
    if (!done) {
        asm volatile(
            "{\n\t.reg .pred P1;\n\t"
            "WAIT_LOOP_%=:\n\t"
            "mbarrier.try_wait.parity.acquire.cta.shared::cta.b64 P1, [%0], %1, 0x989680;\n\t"
            "@P1 bra.uni WAIT_DONE_%=;\n\t"
            "bra.uni WAIT_LOOP_%=;\n\t"
            "WAIT_DONE_%=:\n\t}"
            :: "r"(mbar), "r"(parity) : "memory");
    }
}
#define CLUSTER_SYNC() do {                                              \
    asm volatile("barrier.cluster.arrive.aligned;" ::: "memory");        \
    asm volatile("barrier.cluster.wait.aligned;"   ::: "memory");        \
} while (0)

// ---------------------------------------------------------------------------
// 2 neurons per thread. Warp g (global) owns neurons [64g, 64g+64):
//   lane l -> neurons 64g+l (word 2g) and 64g+32+l (word 2g+1).
// One st.async.b64 per warp delivers both words; a CTA's step mbarrier
// completes when all 64 words (256 tx bytes, 32 b64 stores) have landed.
__global__ __launch_bounds__(THREADS)
__cluster_dims__(NCTAS, 1, 1)
void recurrent_kernel(
    const int*   __restrict__ input_bits,
    const int*   __restrict__ conn_state,
    const float* __restrict__ state_table,
    const int*   __restrict__ conn_out,
    const float* __restrict__ output_table,
    float*       __restrict__ out)
{
    __shared__ __align__(16) unsigned sbits[SBITS_WORDS];
    __shared__ __align__(8)  unsigned long long mbar[2];

    const int tid  = threadIdx.x;
    const int lane = tid & 31;
    const int warp = tid >> 5;                       // 0..3
    const uint32_t rank = cluster_rank();
    const int g  = (int)rank * WARPS + warp;         // global warp 0..31
    const int n0 = g * 64 + lane;                    // first neuron
    const int n1 = n0 + 32;                          // second neuron

    const uint32_t sb = smem_u32(sbits);
    const uint32_t mb = smem_u32(mbar);

    // ---- startup: pack all 64 windows into smem, one word per (thread,k) ----
#pragma unroll
    for (int k = 0; k < WIN_WORDS / THREADS; k++) {
        const int W = k * THREADS + tid;             // 0..2047
        const int4* p = reinterpret_cast<const int4*>(input_bits) + W * 8;
        unsigned bword = 0;
#pragma unroll
        for (int q = 0; q < 8; q++) {
            const int4 v = p[q];
            bword |= ((unsigned)v.x << (q * 4 + 0))
                   | ((unsigned)v.y << (q * 4 + 1))
                   | ((unsigned)v.z << (q * 4 + 2))
                   | ((unsigned)v.w << (q * 4 + 3));
        }
        sbits[W] = bword;
    }
    // zero both state buffers (t=0 reads buffer 0 => all-zero initial state)
    sbits[STATE_BASE + tid] = 0u;                    // 128 words, 128 threads

    // ---- mbarrier setup: arm = 1 arrive + 256 tx bytes per phase ------------
    if (tid == 0) {
        mbar_init(mb + 0, 1);
        mbar_init(mb + 8, 1);
        mbar_arrive(mb + 0);                 // burn phase 0 of mbar[0] (no step-0 wait)
        mbar_arm_tx(mb + 0, STEP_TX_BYTES);  // arm mbar[0] phase 1  -> step 2
        mbar_arm_tx(mb + 8, STEP_TX_BYTES);  // arm mbar[1] phase 0  -> step 1
    }

    // ---- preload connections for both neurons, encoded (word<<5 | shift) ----
    int enc0[16], enc1[16];
    {
        const int4* c4 = reinterpret_cast<const int4*>(conn_state);
#pragma unroll
        for (int h = 0; h < 2; h++) {
            const int nn = h ? n1 : n0;
            int* enc = h ? enc1 : enc0;
            int4 a0 = c4[nn*4+0], a1 = c4[nn*4+1], a2 = c4[nn*4+2], a3 = c4[nn*4+3];
            int raw[16] = { a0.x,a0.y,a0.z,a0.w, a1.x,a1.y,a1.z,a1.w,
                            a2.x,a2.y,a2.z,a2.w, a3.x,a3.y,a3.z,a3.w };
#pragma unroll
            for (int j = 0; j < 16; j++) {
                const int ci = raw[j];
                const int sh = ci & 31;
                const int base = (ci < INPUT_BITS) ? (ci >> 5)
                                                   : (STATE_BASE + ((ci - INPUT_BITS) >> 5));
                enc[j] = (base << 5) | sh;
            }
        }
    }
    const float* trow0 = state_table + (size_t)n0 * HASH;
    const float* trow1 = state_table + (size_t)n1 * HASH;

    // ---- precompute push targets for both parities (lanes 0..NCTAS-1) -------
    // destination: words {2g, 2g+1} of buffer p in CTA `lane` (8B aligned).
    uint32_t rdata0 = 0, rdata1 = 0, rmbar0 = 0, rmbar1 = 0;
    if (lane < NCTAS) {
        const uint32_t w0 = (uint32_t)(STATE_BASE + 0)  + 2u * (uint32_t)g;
        const uint32_t w1 = (uint32_t)(STATE_BASE + 64) + 2u * (uint32_t)g;
        rdata0 = mapa_u32(sb + (w0 << 2), (uint32_t)lane);
        rdata1 = mapa_u32(sb + (w1 << 2), (uint32_t)lane);
        rmbar0 = mapa_u32(mb + 0, (uint32_t)lane);
        rmbar1 = mapa_u32(mb + 8, (uint32_t)lane);
    }

    __syncthreads();        // smem init complete within CTA
    CLUSTER_SYNC();         // all CTAs' smem + armed mbarriers visible cluster-wide

    // ---- step 0 (peeled: no wait, state all zeros, woff = boff = 0) ---------
    {
        unsigned acc0 = 0, acc1 = 0;
#pragma unroll
        for (int j = 0; j < 16; j++) {
            const int e0 = enc0[j];
            acc0 |= ((sbits[e0 >> 5] >> (e0 & 31)) & 1u) << j;
            const int e1 = enc1[j];
            acc1 |= ((sbits[e1 >> 5] >> (e1 & 31)) & 1u) << j;
        }
        const float v0 = __ldg(trow0 + acc0);
        const float v1 = __ldg(trow1 + acc1);
        const unsigned bal0 = __ballot_sync(0xffffffffu, v0 > 0.5f);
        const unsigned bal1 = __ballot_sync(0xffffffffu, v1 > 0.5f);
        if (lane < NCTAS)
            st_async_u64(rdata1,
                         (unsigned long long)bal0 | ((unsigned long long)bal1 << 32),
                         rmbar1);            // t+1 = 1 -> buffer 1 / mbar 1
    }

    // ---- steps 1..63: wait = arrival of all 64 state words -------------------
    for (int t = 1; t < T_STEPS; t++) {
        const uint32_t m = mb + ((unsigned)(t & 1) << 3);
        mbar_wait_parity(m, (unsigned)(t >> 1) & 1u);

        const int woff = t << 5;                     // window word offset
        const int boff = (t & 1) << 6;               // state read-buffer offset

        unsigned acc0 = 0, acc1 = 0;
#pragma unroll
        for (int j = 0; j < 16; j++) {
            const int e0 = enc0[j], b0 = e0 >> 5;
            const int i0 = b0 + ((b0 < STATE_BASE) ? woff : boff);
            acc0 |= ((sbits[i0] >> (e0 & 31)) & 1u) << j;
            const int e1 = enc1[j], b1 = e1 >> 5;
            const int i1 = b1 + ((b1 < STATE_BASE) ? woff : boff);
            acc1 |= ((sbits[i1] >> (e1 & 31)) & 1u) << j;
        }

        const float v0 = __ldg(trow0 + acc0);
        const float v1 = __ldg(trow1 + acc1);
        const unsigned bal0 = __ballot_sync(0xffffffffu, v0 > 0.5f);
        const unsigned bal1 = __ballot_sync(0xffffffffu, v1 > 0.5f);

        // re-arm for step t+2 (off the gather/LDG path; still program-ordered
        // before lane 0's push, which peers need before any t+2 store arrives)
        if (tid == 0)
            mbar_arm_tx(m, STEP_TX_BYTES);

        // one b64 push per warp into ALL cluster CTAs' next-state buffer
        if (lane < NCTAS) {
            const unsigned p1 = (unsigned)((t + 1) & 1);
            st_async_u64(p1 ? rdata1 : rdata0,
                         (unsigned long long)bal0 | ((unsigned long long)bal1 << 32),
                         p1 ? rmbar1 : rmbar0);
        }
    }

    // ---- final wait: no CTA exits with incoming st.async in flight ----------
    // step "64": mbar[0], phase 32 -> parity 0; final state lands in buffer 0.
    mbar_wait_parity(mb + 0, 0u);

    if (rank == 0) {
#pragma unroll
        for (int o = tid; o < N_OUT; o += THREADS) {
            const int4* c4 = reinterpret_cast<const int4*>(conn_out) + o * 4;
            int4 a0 = c4[0], a1 = c4[1], a2 = c4[2], a3 = c4[3];
            int co[16] = { a0.x,a0.y,a0.z,a0.w, a1.x,a1.y,a1.z,a1.w,
                           a2.x,a2.y,a2.z,a2.w, a3.x,a3.y,a3.z,a3.w };
            unsigned addr = 0;
#pragma unroll
            for (int j = 0; j < 16; j++) {
                const int ci = co[j];
                addr |= ((sbits[STATE_BASE + (ci >> 5)] >> (ci & 31)) & 1u) << j;
            }
            out[o] = __ldg(output_table + (size_t)o * HASH + addr);
        }
    }
}

// ---------------------------------------------------------------------------
extern "C" void kernel_launch(void* const* d_in, const int* in_sizes, int n_in,
                              void* d_out, int out_size)
{
    const int*   input_bits   = (const int*)  d_in[0];  // [65536]
    const int*   conn_state   = (const int*)  d_in[1];  // [2048*16]
    const int*   conn_out     = (const int*)  d_in[2];  // [256*16]
    const float* state_table  = (const float*)d_in[3];  // [2048*65536]
    const float* output_table = (const float*)d_in[4];  // [256*65536]
    float*       out          = (float*)d_out;          // [256]

    recurrent_kernel<<<NCTAS, THREADS>>>(
        input_bits, conn_state, state_table, conn_out, output_table, out);
}